// round 15
// baseline (speedup 1.0000x reference)
#include <cuda_runtime.h>

// CRPS loss — FINAL (best measured: bench 10.72us, ncu 9.44us).
// 2 pixels per thread, all 34 scalar LDG.32 front-batched (highest measured
// effective BW of 8 tested structures). Single wave: 512 blocks @ 4/SM.
// term2 per pixel via sort identity sum_{i<j}|xi-xj| = sum_k (2k-15)x_(k),
// 16-elem Batcher network (63 FMNMX pairs, ALU pipe).

#define NS   16
#define P    262144
#define NT   256
#define PX   2
#define NB   (P / (NT * PX))    // 512 blocks
#define STRIDE (NB * NT)        // 131072

__device__ float        g_partial[NB];
__device__ unsigned int g_count = 0;

__device__ __forceinline__ void cas(float& a, float& b) {
    float lo = fminf(a, b);
    float hi = fmaxf(a, b);
    a = lo; b = hi;
}

__device__ __forceinline__ float crps_px(float v[NS], float t) {
    // term1: sum_i |s_i - y|
    float a1 = 0.f;
#pragma unroll
    for (int i = 0; i < NS; i++) a1 += fabsf(v[i] - t);

    // Batcher odd-even mergesort, n=16 (63 CAS)
#pragma unroll
    for (int pp = 1; pp < NS; pp <<= 1) {
#pragma unroll
        for (int k = pp; k >= 1; k >>= 1) {
#pragma unroll
            for (int j = k % pp; j + k < NS; j += 2 * k) {
#pragma unroll
                for (int i = 0; i < k && i + j + k < NS; i++) {
                    if ((i + j) / (2 * pp) == (i + j + k) / (2 * pp))
                        cas(v[i + j], v[i + j + k]);
                }
            }
        }
    }

    // term2 raw: sum_k (2k-15) x_(k)
    float a2 = 0.f;
#pragma unroll
    for (int k = 0; k < NS; k++)
        a2 = fmaf((float)(2 * k - 15), v[k], a2);

    return a1 * (1.0f / 16.0f) - a2 * (1.0f / 256.0f);
}

__global__ void __launch_bounds__(NT, 4)
k_crps(const float* __restrict__ s, const float* __restrict__ y,
       float* __restrict__ out) {
    const int p0 = blockIdx.x * NT + threadIdx.x;
    const int p1 = p0 + STRIDE;

    // Front-batched loads for BOTH pixels: 32 sample LDGs + 2 target LDGs
    // independent and in flight together.
    float v0[NS], v1[NS];
#pragma unroll
    for (int i = 0; i < NS; i++) v0[i] = __ldg(&s[i * P + p0]);
#pragma unroll
    for (int i = 0; i < NS; i++) v1[i] = __ldg(&s[i * P + p1]);
    const float t0 = __ldg(&y[p0]);
    const float t1 = __ldg(&y[p1]);

    // Compute px0 while px1's loads may still be landing, then px1.
    float val = crps_px(v0, t0);
    val      += crps_px(v1, t1);

    // Block reduction
#pragma unroll
    for (int o = 16; o > 0; o >>= 1)
        val += __shfl_xor_sync(0xFFFFFFFFu, val, o);

    __shared__ float sm[NT / 32];
    const int lane = threadIdx.x & 31;
    const int wid  = threadIdx.x >> 5;
    if (lane == 0) sm[wid] = val;
    __syncthreads();

    if (wid == 0) {
        float w = (lane < NT / 32) ? sm[lane] : 0.f;
#pragma unroll
        for (int o = 4; o > 0; o >>= 1)
            w += __shfl_xor_sync(0xFFFFFFFFu, w, o);
        if (lane == 0) g_partial[blockIdx.x] = w;
    }

    // Last-block finalize (counter self-resets -> graph-replay deterministic)
    __shared__ bool isLast;
    if (threadIdx.x == 0) {
        __threadfence();
        isLast = (atomicAdd(&g_count, 1u) == NB - 1);
    }
    __syncthreads();

    if (isLast) {
        double d = 0.0;
#pragma unroll
        for (int r = 0; r < NB / NT; r++)
            d += (double)g_partial[threadIdx.x + r * NT];
#pragma unroll
        for (int o = 16; o > 0; o >>= 1)
            d += __shfl_xor_sync(0xFFFFFFFFu, d, o);

        __shared__ double sd[NT / 32];
        if (lane == 0) sd[wid] = d;
        __syncthreads();
        if (wid == 0) {
            double e = (lane < NT / 32) ? sd[lane] : 0.0;
#pragma unroll
            for (int o = 4; o > 0; o >>= 1)
                e += __shfl_xor_sync(0xFFFFFFFFu, e, o);
            if (lane == 0) {
                *out = (float)(e * (1.0 / (double)P));
                g_count = 0;
            }
        }
    }
}

extern "C" void kernel_launch(void* const* d_in, const int* in_sizes, int n_in,
                              void* d_out, int out_size) {
    const float* samples = (const float*)d_in[0];
    const float* target  = (const float*)d_in[1];
    k_crps<<<NB, NT>>>(samples, target, (float*)d_out);
}